// round 3
// baseline (speedup 1.0000x reference)
#include <cuda_runtime.h>
#include <cstdint>

// ---------------------------------------------------------------------------
// Problem constants (fixed by setup_inputs)
// ---------------------------------------------------------------------------
#define TDOCS 4096
#define TSEQ  64
#define DIM   128
#define HID   128
#define GATES 512      // 4*HID
#define TILE1 32       // docs per CTA (layer 1)
#define KC1   32       // k-chunk (layer 1)
#define NCH1  8        // 256 / 32

#define NNODES 512     // G*N = 8*64
#define KSTEPS 8
#define HID2   64
#define GATES2 256     // 4*HID2
#define KTOT2  320     // 256 (x) + 64 (h)
#define TILE2  8
#define KC2    64
#define NCH2   5       // 320 / 64

// ---------------------------------------------------------------------------
// Device scratch (static; no allocations anywhere)
// ---------------------------------------------------------------------------
__device__ float g_Wt1[2 * 256 * GATES];      // [dir][k][gate], k<128 = ih, k>=128 = hh   (1 MB)
__device__ float g_Wt2[2 * KTOT2 * GATES2];   // [dir][k][gate], k<256 = ih, k>=256 = hh   (640 KB)
__device__ float g_demb[TDOCS * 256];         // doc embeddings [doc][dir*128 + h]         (4 MB)
__device__ int   g_perm[TDOCS];               // docs sorted by length, descending

// ---------------------------------------------------------------------------
// Helpers
// ---------------------------------------------------------------------------
__device__ __forceinline__ float sigf(float x) {
    return __fdividef(1.f, 1.f + __expf(-x));
}
__device__ __forceinline__ float tanh_f(float x) {
    // tanh(x) = 2*sigmoid(2x) - 1  (MUFU.EX2 + fast rcp; abs err ~1e-7)
    return fmaf(2.f, __fdividef(1.f, 1.f + __expf(-2.f * x)), -1.f);
}
__device__ __forceinline__ void cp_async16(void* dst_smem, const void* src_gmem) {
    unsigned s = (unsigned)__cvta_generic_to_shared(dst_smem);
    asm volatile("cp.async.ca.shared.global [%0], [%1], 16;\n" :: "r"(s), "l"(src_gmem));
}
__device__ __forceinline__ void cp_commit() { asm volatile("cp.async.commit_group;\n"); }
__device__ __forceinline__ void cp_wait1()  { asm volatile("cp.async.wait_group 1;\n"); }
__device__ __forceinline__ void cp_wait0()  { asm volatile("cp.async.wait_group 0;\n"); }

// ---------------------------------------------------------------------------
// Prep: transpose weights to k-major (so chunk loads are contiguous copies)
// ---------------------------------------------------------------------------
__global__ void transpose1_kernel(const float* __restrict__ Wihf, const float* __restrict__ Whhf,
                                  const float* __restrict__ Wihb, const float* __restrict__ Whhb) {
    int g = blockIdx.x;          // 0..511 (gate)
    int k = threadIdx.x;         // 0..255
    int dir = blockIdx.y;
    const float* Wih = dir ? Wihb : Wihf;
    const float* Whh = dir ? Whhb : Whhf;
    float v = (k < 128) ? Wih[g * 128 + k] : Whh[g * 128 + (k - 128)];
    g_Wt1[((size_t)dir * 256 + k) * GATES + g] = v;
}

__global__ void transpose2_kernel(const float* __restrict__ Wihf, const float* __restrict__ Whhf,
                                  const float* __restrict__ Wihb, const float* __restrict__ Whhb) {
    int g = blockIdx.x;          // 0..255 (gate)
    int k = threadIdx.x;         // 0..319
    int dir = blockIdx.y;
    const float* Wih = dir ? Wihb : Wihf;
    const float* Whh = dir ? Whhb : Whhf;
    float v = (k < 256) ? Wih[g * 256 + k] : Whh[g * 64 + (k - 256)];
    g_Wt2[((size_t)dir * KTOT2 + k) * GATES2 + g] = v;
}

// ---------------------------------------------------------------------------
// Prep: counting sort of docs by length, DESCENDING (longest tiles scheduled
// first -> good tail behavior). Order within a length-bin is atomic-
// nondeterministic, but per-doc outputs are independent of tile composition,
// so results are bitwise identical regardless of permutation.
// ---------------------------------------------------------------------------
__global__ void sort_kernel(const int* __restrict__ lens) {
    __shared__ int hist[TSEQ + 1];
    __shared__ int cur[TSEQ + 1];
    int tid = threadIdx.x;
    if (tid <= TSEQ) hist[tid] = 0;
    __syncthreads();
    for (int i = tid; i < TDOCS; i += blockDim.x) atomicAdd(&hist[lens[i]], 1);
    __syncthreads();
    if (tid == 0) {
        int acc = 0;
        for (int l = TSEQ; l >= 1; l--) { cur[l] = acc; acc += hist[l]; }
    }
    __syncthreads();
    for (int i = tid; i < TDOCS; i += blockDim.x) {
        int l = lens[i];
        int p = atomicAdd(&cur[l], 1);
        g_perm[p] = i;
    }
}

// ---------------------------------------------------------------------------
// Layer 1: BiLSTM over docs, mean-pooled. One CTA = 32 docs x 1 direction.
// smem: xh[256][32] (x_t | h), c[128][32], sum[128][32], Wbuf[2][32][512]
// Thread micro-tile: 4 docs x (4 hids x 4 gate-types) = 64 accumulators.
// All four gates of a hid land in the SAME thread -> local state update.
// ---------------------------------------------------------------------------
__global__ void __launch_bounds__(256, 1)
lstm1_kernel(const float* __restrict__ docs, const int* __restrict__ lens) {
    extern __shared__ float sm[];
    float* xh = sm;                       // [256][32]: k<128 x_t, k>=128 h
    float* cs = sm + 8192;                // [128][32]
    float* ss = sm + 12288;               // [128][32]
    float* wb = sm + 16384;               // [2][KC1][512] double buffer
    int*   Ls  = (int*)(sm + 16384 + 2 * KC1 * GATES);   // [32]
    int*   Did = Ls + TILE1;                              // [32]

    const int tid  = threadIdx.x;
    const int dir  = blockIdx.y;
    const int tile = blockIdx.x;
    const float* Wt = g_Wt1 + (size_t)dir * 256 * GATES;

    if (tid < TILE1) {
        int d = g_perm[tile * TILE1 + tid];
        Did[tid] = d;
        Ls[tid]  = lens[d];
    }
    // zero h-part of xh (4096..8191), c (8192..12287), sum (12288..16383)
    for (int i = tid; i < 12288; i += 256) sm[4096 + i] = 0.f;
    __syncthreads();

    int maxlen = 0;
    #pragma unroll 8
    for (int i = 0; i < TILE1; i++) maxlen = max(maxlen, Ls[i]);

    const int dg = tid & 7;    // doc group: docs 4*dg..4*dg+3
    const int gq = tid >> 3;   // hid group: hids 4*gq..4*gq+3 (0..31)
    const int xd = tid >> 3;   // x-load: doc 0..31
    const int xj = tid & 7;    // x-load: 16-float slice

    for (int st = 0; st < maxlen; ++st) {
        // issue chunk 0 of W for this step
        {
            const float4* src = (const float4*)Wt + tid;
            float4* dst = (float4*)wb + tid;
            #pragma unroll
            for (int q = 0; q < 16; q++) cp_async16(dst + 256 * q, src + 256 * q);
            cp_commit();
        }
        // load x_t for each doc (transposed into xh[k][d])
        {
            int L  = Ls[xd];
            int te = (dir == 0) ? st : (L - 1 - st);
            te = min(max(te, 0), TSEQ - 1);                 // clamp; inactive docs masked later
            const float4* row = (const float4*)(docs + ((size_t)Did[xd] * TSEQ + te) * DIM);
            #pragma unroll
            for (int r = 0; r < 4; r++) {
                float4 v = row[xj * 4 + r];
                int k0 = xj * 16 + r * 4;
                xh[(k0 + 0) * TILE1 + xd] = v.x;
                xh[(k0 + 1) * TILE1 + xd] = v.y;
                xh[(k0 + 2) * TILE1 + xd] = v.z;
                xh[(k0 + 3) * TILE1 + xd] = v.w;
            }
        }
        __syncthreads();

        float acc[4][4][4];   // [gate-type][hid][doc]
        #pragma unroll
        for (int b = 0; b < 4; b++)
            #pragma unroll
            for (int j = 0; j < 4; j++)
                #pragma unroll
                for (int d2 = 0; d2 < 4; d2++) acc[b][j][d2] = 0.f;

        // K = 256 in 8 chunks, double-buffered cp.async
        for (int n = 0; n < NCH1; n++) {
            if (n + 1 < NCH1) {
                const float4* src = (const float4*)(Wt + (size_t)(n + 1) * KC1 * GATES) + tid;
                float4* dst = (float4*)(wb + ((n + 1) & 1) * (KC1 * GATES)) + tid;
                #pragma unroll
                for (int q = 0; q < 16; q++) cp_async16(dst + 256 * q, src + 256 * q);
                cp_commit();
                cp_wait1();
            } else {
                cp_wait0();
            }
            __syncthreads();

            const float* W  = wb + (n & 1) * (KC1 * GATES);
            const float* xk = xh + n * KC1 * TILE1;
            #pragma unroll 4
            for (int kc = 0; kc < KC1; kc++) {
                float4 xv = *(const float4*)(xk + kc * TILE1 + (dg << 2));
                float xa[4] = { xv.x, xv.y, xv.z, xv.w };
                #pragma unroll
                for (int b = 0; b < 4; b++) {
                    float4 wv = *(const float4*)(W + kc * GATES + b * HID + (gq << 2));
                    float wa[4] = { wv.x, wv.y, wv.z, wv.w };
                    #pragma unroll
                    for (int j = 0; j < 4; j++)
                        #pragma unroll
                        for (int d2 = 0; d2 < 4; d2++)
                            acc[b][j][d2] = fmaf(wa[j], xa[d2], acc[b][j][d2]);
                }
            }
            __syncthreads();
        }

        // state update: thread owns (4 hids x 4 docs), fully local i/f/g/o
        {
            const int dbase = dg << 2;
            int Lloc[4];
            #pragma unroll
            for (int d2 = 0; d2 < 4; d2++) Lloc[d2] = Ls[dbase + d2];
            #pragma unroll
            for (int j = 0; j < 4; j++) {
                int h = (gq << 2) + j;
                float4 co = *(float4*)(cs + h * TILE1 + dbase);
                float4 ho = *(float4*)(xh + (128 + h) * TILE1 + dbase);
                float4 so = *(float4*)(ss + h * TILE1 + dbase);
                float ca[4] = { co.x, co.y, co.z, co.w };
                float ha[4] = { ho.x, ho.y, ho.z, ho.w };
                float sa[4] = { so.x, so.y, so.z, so.w };
                #pragma unroll
                for (int d2 = 0; d2 < 4; d2++) {
                    float ig = sigf(acc[0][j][d2]);
                    float fg = sigf(acc[1][j][d2]);
                    float gg = tanh_f(acc[2][j][d2]);
                    float og = sigf(acc[3][j][d2]);
                    float c2v = fmaf(fg, ca[d2], ig * gg);
                    float h2v = og * tanh_f(c2v);
                    if (st < Lloc[d2]) {
                        ca[d2] = c2v;
                        ha[d2] = h2v;
                        sa[d2] += h2v;
                    }
                }
                *(float4*)(cs + h * TILE1 + dbase) = make_float4(ca[0], ca[1], ca[2], ca[3]);
                *(float4*)(xh + (128 + h) * TILE1 + dbase) = make_float4(ha[0], ha[1], ha[2], ha[3]);
                *(float4*)(ss + h * TILE1 + dbase) = make_float4(sa[0], sa[1], sa[2], sa[3]);
            }
        }
        __syncthreads();
    }

    // epilogue: doc_emb[doc][dir*128 + h] = sum / len
    {
        const int dbase = dg << 2;
        #pragma unroll
        for (int j = 0; j < 4; j++) {
            int h = (gq << 2) + j;
            #pragma unroll
            for (int d2 = 0; d2 < 4; d2++) {
                int d = dbase + d2;
                float v = ss[h * TILE1 + d] / (float)Ls[d];
                g_demb[(size_t)Did[d] * 256 + dir * 128 + h] = v;
            }
        }
    }
}

// ---------------------------------------------------------------------------
// Layer 2: BiLSTM over nodes (K<=8 steps, input 256, H2=64) + mask + output.
// One CTA = 8 nodes x 1 direction. Thread: 1 hid x 4 gate-types x 2 nodes.
// ---------------------------------------------------------------------------
__global__ void __launch_bounds__(256, 1)
lstm2_kernel(const int* __restrict__ nidx, const int* __restrict__ nlens,
             const int* __restrict__ gnum, float* __restrict__ out) {
    extern __shared__ float sm[];
    float* xh = sm;                 // [320][8]: k<256 x, k>=256 h
    float* cs = sm + 2560;          // [64][8]
    float* ss = sm + 3072;          // [64][8]
    float* wb = sm + 3584;          // [2][KC2][256]
    int*   Ls = (int*)(sm + 3584 + 2 * KC2 * GATES2);    // [8]

    const int tid  = threadIdx.x;
    const int dir  = blockIdx.y;
    const int tile = blockIdx.x;
    const float* Wt = g_Wt2 + (size_t)dir * KTOT2 * GATES2;

    if (tid < TILE2) Ls[tid] = nlens[tile * TILE2 + tid];
    // zero h-part of xh (2048..2559), c (2560..3071), sum (3072..3583)
    for (int i = tid; i < 1536; i += 256) sm[2048 + i] = 0.f;
    __syncthreads();

    int maxlen = 0;
    #pragma unroll
    for (int i = 0; i < TILE2; i++) maxlen = max(maxlen, Ls[i]);

    const int ng = tid & 3;     // node group: nodes 2*ng, 2*ng+1
    const int hh = tid >> 2;    // hid 0..63
    const int xn = tid >> 5;    // x-gather: node 0..7
    const int xq = tid & 31;    // x-gather: 8-float slice

    for (int st = 0; st < maxlen; ++st) {
        // issue W chunk 0
        {
            const float4* src = (const float4*)Wt + tid;
            float4* dst = (float4*)wb + tid;
            #pragma unroll
            for (int q = 0; q < 16; q++) cp_async16(dst + 256 * q, src + 256 * q);
            cp_commit();
        }
        // gather x from doc embeddings
        {
            int L  = Ls[xn];
            int te = (dir == 0) ? st : (L - 1 - st);
            te = min(max(te, 0), KSTEPS - 1);
            int gn = tile * TILE2 + xn;
            int didx = nidx[gn * KSTEPS + te];
            const float4* row = (const float4*)(g_demb + (size_t)didx * 256);
            #pragma unroll
            for (int r = 0; r < 2; r++) {
                float4 v = row[xq * 2 + r];
                int k0 = xq * 8 + r * 4;
                xh[(k0 + 0) * TILE2 + xn] = v.x;
                xh[(k0 + 1) * TILE2 + xn] = v.y;
                xh[(k0 + 2) * TILE2 + xn] = v.z;
                xh[(k0 + 3) * TILE2 + xn] = v.w;
            }
        }
        __syncthreads();

        float acc[4][2];
        #pragma unroll
        for (int b = 0; b < 4; b++) { acc[b][0] = 0.f; acc[b][1] = 0.f; }

        for (int n = 0; n < NCH2; n++) {
            if (n + 1 < NCH2) {
                const float4* src = (const float4*)(Wt + (size_t)(n + 1) * KC2 * GATES2) + tid;
                float4* dst = (float4*)(wb + ((n + 1) & 1) * (KC2 * GATES2)) + tid;
                #pragma unroll
                for (int q = 0; q < 16; q++) cp_async16(dst + 256 * q, src + 256 * q);
                cp_commit();
                cp_wait1();
            } else {
                cp_wait0();
            }
            __syncthreads();

            const float* W  = wb + (n & 1) * (KC2 * GATES2);
            const float* xk = xh + n * KC2 * TILE2;
            #pragma unroll 4
            for (int kc = 0; kc < KC2; kc++) {
                float2 xv = *(const float2*)(xk + kc * TILE2 + (ng << 1));
                #pragma unroll
                for (int b = 0; b < 4; b++) {
                    float w = W[kc * GATES2 + b * HID2 + hh];
                    acc[b][0] = fmaf(w, xv.x, acc[b][0]);
                    acc[b][1] = fmaf(w, xv.y, acc[b][1]);
                }
            }
            __syncthreads();
        }

        // state update
        {
            #pragma unroll
            for (int e = 0; e < 2; e++) {
                int nd = (ng << 1) + e;
                float co = cs[hh * TILE2 + nd];
                float ho = xh[(256 + hh) * TILE2 + nd];
                float so = ss[hh * TILE2 + nd];
                float ig = sigf(acc[0][e]);
                float fg = sigf(acc[1][e]);
                float gg = tanh_f(acc[2][e]);
                float og = sigf(acc[3][e]);
                float c2v = fmaf(fg, co, ig * gg);
                float h2v = og * tanh_f(c2v);
                bool act = st < Ls[nd];
                cs[hh * TILE2 + nd] = act ? c2v : co;
                xh[(256 + hh) * TILE2 + nd] = act ? h2v : ho;
                ss[hh * TILE2 + nd] = act ? (so + h2v) : so;
            }
        }
        __syncthreads();
    }

    // epilogue: masked output + gmask
    {
        #pragma unroll
        for (int e = 0; e < 2; e++) {
            int nd = (ng << 1) + e;
            int gn = tile * TILE2 + nd;
            int gi = gn >> 6;
            int ni = gn & 63;
            float gm = (ni < gnum[gi]) ? 1.f : 0.f;
            float v = ss[hh * TILE2 + nd] / (float)Ls[nd] * gm;
            out[(size_t)gn * 128 + dir * 64 + hh] = v;
            if (dir == 0 && hh == 0) out[NNODES * 128 + gn] = gm;
        }
    }
}

// ---------------------------------------------------------------------------
// Launch
// ---------------------------------------------------------------------------
extern "C" void kernel_launch(void* const* d_in, const int* in_sizes, int n_in,
                              void* d_out, int out_size) {
    const float* docs  = (const float*)d_in[0];
    const int*   dlens = (const int*)  d_in[1];
    const int*   nidx  = (const int*)  d_in[2];
    const int*   nlens = (const int*)  d_in[3];
    const int*   gnum  = (const int*)  d_in[4];
    const float* Wih1f = (const float*)d_in[5];
    const float* Whh1f = (const float*)d_in[6];
    const float* Wih1b = (const float*)d_in[7];
    const float* Whh1b = (const float*)d_in[8];
    const float* Wih2f = (const float*)d_in[9];
    const float* Whh2f = (const float*)d_in[10];
    const float* Wih2b = (const float*)d_in[11];
    const float* Whh2b = (const float*)d_in[12];
    float* out = (float*)d_out;

    const size_t sm1 = (size_t)(16384 + 2 * KC1 * GATES) * 4 + (TILE1 * 2) * 4;    // 196864 B
    const size_t sm2 = (size_t)(3584 + 2 * KC2 * GATES2) * 4 + TILE2 * 4 + 32;     // ~145472 B
    cudaFuncSetAttribute(lstm1_kernel, cudaFuncAttributeMaxDynamicSharedMemorySize, (int)sm1);
    cudaFuncSetAttribute(lstm2_kernel, cudaFuncAttributeMaxDynamicSharedMemorySize, (int)sm2);

    transpose1_kernel<<<dim3(512, 2), 256>>>(Wih1f, Whh1f, Wih1b, Whh1b);
    transpose2_kernel<<<dim3(256, 2), 320>>>(Wih2f, Whh2f, Wih2b, Whh2b);
    sort_kernel<<<1, 1024>>>(dlens);
    lstm1_kernel<<<dim3(TDOCS / TILE1, 2), 256, sm1>>>(docs, dlens);
    lstm2_kernel<<<dim3(NNODES / TILE2, 2), 256, sm2>>>(nidx, nlens, gnum, out);
    (void)in_sizes; (void)n_in; (void)out_size;
}

// round 6
// speedup vs baseline: 1.0488x; 1.0488x over previous
#include <cuda_runtime.h>
#include <cstdint>

// ---------------------------------------------------------------------------
// Problem constants (fixed by setup_inputs)
// ---------------------------------------------------------------------------
#define TDOCS 4096
#define TSEQ  64
#define DIM   128
#define HID   128
#define GATES 512      // 4*HID
#define TILE1 32       // docs per CTA (layer 1)
#define KC1   32       // k-chunk (layer 1)
#define NCH1  8        // 256 / 32

#define NNODES 512     // G*N = 8*64
#define KSTEPS 8
#define HID2   64
#define GATES2 256     // 4*HID2
#define KTOT2  320     // 256 (x) + 64 (h)
#define TILE2  8
#define KC2    64
#define NCH2   5       // 320 / 64

// ---------------------------------------------------------------------------
// Device scratch (static; no allocations anywhere)
// ---------------------------------------------------------------------------
__device__ float g_Wt1[2 * 256 * GATES];      // [dir][k][gate], k<128 = ih, k>=128 = hh   (1 MB)
__device__ float g_Wt2[2 * KTOT2 * GATES2];   // [dir][k][gate], k<256 = ih, k>=256 = hh   (640 KB)
__device__ float g_demb[TDOCS * 256];         // doc embeddings [doc][dir*128 + h]         (4 MB)
__device__ int   g_perm[TDOCS];               // docs sorted by length, descending

// ---------------------------------------------------------------------------
// Helpers
// ---------------------------------------------------------------------------
__device__ __forceinline__ float sigf(float x) {
    return __fdividef(1.f, 1.f + __expf(-x));
}
__device__ __forceinline__ float tanh_f(float x) {
    // tanh(x) = 2*sigmoid(2x) - 1  (MUFU.EX2 + fast rcp; abs err ~1e-7)
    return fmaf(2.f, __fdividef(1.f, 1.f + __expf(-2.f * x)), -1.f);
}
__device__ __forceinline__ void cp_async16(void* dst_smem, const void* src_gmem) {
    unsigned s = (unsigned)__cvta_generic_to_shared(dst_smem);
    asm volatile("cp.async.ca.shared.global [%0], [%1], 16;\n" :: "r"(s), "l"(src_gmem));
}
__device__ __forceinline__ void cp_commit() { asm volatile("cp.async.commit_group;\n"); }
__device__ __forceinline__ void cp_wait1()  { asm volatile("cp.async.wait_group 1;\n"); }
__device__ __forceinline__ void cp_wait0()  { asm volatile("cp.async.wait_group 0;\n"); }

// Packed fp32x2 (Blackwell): one fma-pipe instruction, two fp32 MACs.
__device__ __forceinline__ void ffma2(unsigned long long& d,
                                      unsigned long long a, unsigned long long b) {
    asm("fma.rn.f32x2 %0, %1, %2, %0;" : "+l"(d) : "l"(a), "l"(b));
}
__device__ __forceinline__ unsigned long long dup2(float x) {
    unsigned long long r;
    asm("mov.b64 %0, {%1, %1};" : "=l"(r) : "f"(x));
    return r;
}
__device__ __forceinline__ float2 unpack2(unsigned long long v) {
    float2 r;
    asm("mov.b64 {%0, %1}, %2;" : "=f"(r.x), "=f"(r.y) : "l"(v));
    return r;
}

// ---------------------------------------------------------------------------
// Prep: transpose weights to k-major (so chunk loads are contiguous copies)
// ---------------------------------------------------------------------------
__global__ void transpose1_kernel(const float* __restrict__ Wihf, const float* __restrict__ Whhf,
                                  const float* __restrict__ Wihb, const float* __restrict__ Whhb) {
    int g = blockIdx.x;          // 0..511 (gate)
    int k = threadIdx.x;         // 0..255
    int dir = blockIdx.y;
    const float* Wih = dir ? Wihb : Wihf;
    const float* Whh = dir ? Whhb : Whhf;
    float v = (k < 128) ? Wih[g * 128 + k] : Whh[g * 128 + (k - 128)];
    g_Wt1[((size_t)dir * 256 + k) * GATES + g] = v;
}

__global__ void transpose2_kernel(const float* __restrict__ Wihf, const float* __restrict__ Whhf,
                                  const float* __restrict__ Wihb, const float* __restrict__ Whhb) {
    int g = blockIdx.x;          // 0..255 (gate)
    int k = threadIdx.x;         // 0..319
    int dir = blockIdx.y;
    const float* Wih = dir ? Wihb : Wihf;
    const float* Whh = dir ? Whhb : Whhf;
    float v = (k < 256) ? Wih[g * 256 + k] : Whh[g * 64 + (k - 256)];
    g_Wt2[((size_t)dir * KTOT2 + k) * GATES2 + g] = v;
}

// ---------------------------------------------------------------------------
// Prep: counting sort of docs by length, DESCENDING. Order within a length-
// bin is atomic-nondeterministic, but per-doc outputs are independent of tile
// composition, so results are identical regardless of permutation.
// ---------------------------------------------------------------------------
__global__ void sort_kernel(const int* __restrict__ lens) {
    __shared__ int hist[TSEQ + 1];
    __shared__ int cur[TSEQ + 1];
    int tid = threadIdx.x;
    if (tid <= TSEQ) hist[tid] = 0;
    __syncthreads();
    for (int i = tid; i < TDOCS; i += blockDim.x) atomicAdd(&hist[lens[i]], 1);
    __syncthreads();
    if (tid == 0) {
        int acc = 0;
        for (int l = TSEQ; l >= 1; l--) { cur[l] = acc; acc += hist[l]; }
    }
    __syncthreads();
    for (int i = tid; i < TDOCS; i += blockDim.x) {
        int l = lens[i];
        int p = atomicAdd(&cur[l], 1);
        g_perm[p] = i;
    }
}

// ---------------------------------------------------------------------------
// Layer 1: BiLSTM over docs, mean-pooled. One CTA = 32 docs x 1 direction.
// smem: xh[256][32] (x_t | h), c[128][32], sum[128][32], Wbuf[2][32][512]
// Thread micro-tile: 4 docs x (4 hids x 4 gate-types), hid-dimension packed
// into f32x2 pairs -> 32 FFMA2 per k (was 64 FFMA). W's gate values are
// consecutive in the k-major layout, so one LDS.128 yields two packed
// {w_j0,w_j1} operands with no repacking; only x needs a {x,x} dup.
// ---------------------------------------------------------------------------
__global__ void __launch_bounds__(256, 1)
lstm1_kernel(const float* __restrict__ docs, const int* __restrict__ lens) {
    extern __shared__ float sm[];
    float* xh = sm;                       // [256][32]: k<128 x_t, k>=128 h
    float* cs = sm + 8192;                // [128][32]
    float* ss = sm + 12288;               // [128][32]
    float* wb = sm + 16384;               // [2][KC1][512] double buffer
    int*   Ls  = (int*)(sm + 16384 + 2 * KC1 * GATES);   // [32]
    int*   Did = Ls + TILE1;                              // [32]

    const int tid  = threadIdx.x;
    const int dir  = blockIdx.y;
    const int tile = blockIdx.x;
    const float* Wt = g_Wt1 + (size_t)dir * 256 * GATES;

    if (tid < TILE1) {
        int d = g_perm[tile * TILE1 + tid];
        Did[tid] = d;
        Ls[tid]  = lens[d];
    }
    // zero h-part of xh (4096..8191), c (8192..12287), sum (12288..16383)
    for (int i = tid; i < 12288; i += 256) sm[4096 + i] = 0.f;
    __syncthreads();

    int maxlen = 0;
    #pragma unroll 8
    for (int i = 0; i < TILE1; i++) maxlen = max(maxlen, Ls[i]);

    const int dg = tid & 7;    // doc group: docs 4*dg..4*dg+3
    const int gq = tid >> 3;   // hid group: hids 4*gq..4*gq+3 (0..31)
    const int xd = tid >> 3;   // x-load: doc 0..31
    const int xj = tid & 7;    // x-load: 16-float slice

    for (int st = 0; st < maxlen; ++st) {
        // issue chunk 0 of W for this step
        {
            const float4* src = (const float4*)Wt + tid;
            float4* dst = (float4*)wb + tid;
            #pragma unroll
            for (int q = 0; q < 16; q++) cp_async16(dst + 256 * q, src + 256 * q);
            cp_commit();
        }
        // load x_t for each doc (transposed into xh[k][d])
        {
            int L  = Ls[xd];
            int te = (dir == 0) ? st : (L - 1 - st);
            te = min(max(te, 0), TSEQ - 1);                 // clamp; inactive docs masked later
            const float4* row = (const float4*)(docs + ((size_t)Did[xd] * TSEQ + te) * DIM);
            #pragma unroll
            for (int r = 0; r < 4; r++) {
                float4 v = row[xj * 4 + r];
                int k0 = xj * 16 + r * 4;
                xh[(k0 + 0) * TILE1 + xd] = v.x;
                xh[(k0 + 1) * TILE1 + xd] = v.y;
                xh[(k0 + 2) * TILE1 + xd] = v.z;
                xh[(k0 + 3) * TILE1 + xd] = v.w;
            }
        }
        __syncthreads();

        // acc[b][jp][d]: packed pair {gate(j=2*jp), gate(j=2*jp+1)} for doc d
        unsigned long long acc[4][2][4];
        #pragma unroll
        for (int b = 0; b < 4; b++)
            #pragma unroll
            for (int jp = 0; jp < 2; jp++)
                #pragma unroll
                for (int d2 = 0; d2 < 4; d2++) acc[b][jp][d2] = 0ull;

        // K = 256 in 8 chunks, double-buffered cp.async
        for (int n = 0; n < NCH1; n++) {
            if (n + 1 < NCH1) {
                const float4* src = (const float4*)(Wt + (size_t)(n + 1) * KC1 * GATES) + tid;
                float4* dst = (float4*)(wb + ((n + 1) & 1) * (KC1 * GATES)) + tid;
                #pragma unroll
                for (int q = 0; q < 16; q++) cp_async16(dst + 256 * q, src + 256 * q);
                cp_commit();
                cp_wait1();
            } else {
                cp_wait0();
            }
            __syncthreads();

            const float* W  = wb + (n & 1) * (KC1 * GATES);
            const float* xk = xh + n * KC1 * TILE1;
            #pragma unroll 4
            for (int kc = 0; kc < KC1; kc++) {
                float4 xv = *(const float4*)(xk + kc * TILE1 + (dg << 2));
                unsigned long long xp[4] = { dup2(xv.x), dup2(xv.y), dup2(xv.z), dup2(xv.w) };
                #pragma unroll
                for (int b = 0; b < 4; b++) {
                    ulonglong2 wv = *(const ulonglong2*)(W + kc * GATES + b * HID + (gq << 2));
                    #pragma unroll
                    for (int d2 = 0; d2 < 4; d2++) ffma2(acc[b][0][d2], wv.x, xp[d2]);
                    #pragma unroll
                    for (int d2 = 0; d2 < 4; d2++) ffma2(acc[b][1][d2], wv.y, xp[d2]);
                }
            }
            __syncthreads();
        }

        // unpack packed gate pairs -> ga[b][j][d]
        float ga[4][4][4];
        #pragma unroll
        for (int b = 0; b < 4; b++)
            #pragma unroll
            for (int jp = 0; jp < 2; jp++)
                #pragma unroll
                for (int d2 = 0; d2 < 4; d2++) {
                    float2 p = unpack2(acc[b][jp][d2]);
                    ga[b][2 * jp + 0][d2] = p.x;
                    ga[b][2 * jp + 1][d2] = p.y;
                }

        // state update: thread owns (4 hids x 4 docs), fully local i/f/g/o
        {
            const int dbase = dg << 2;
            int Lloc[4];
            #pragma unroll
            for (int d2 = 0; d2 < 4; d2++) Lloc[d2] = Ls[dbase + d2];
            #pragma unroll
            for (int j = 0; j < 4; j++) {
                int h = (gq << 2) + j;
                float4 co = *(float4*)(cs + h * TILE1 + dbase);
                float4 ho = *(float4*)(xh + (128 + h) * TILE1 + dbase);
                float4 so = *(float4*)(ss + h * TILE1 + dbase);
                float ca[4] = { co.x, co.y, co.z, co.w };
                float ha[4] = { ho.x, ho.y, ho.z, ho.w };
                float sa[4] = { so.x, so.y, so.z, so.w };
                #pragma unroll
                for (int d2 = 0; d2 < 4; d2++) {
                    float ig = sigf(ga[0][j][d2]);
                    float fg = sigf(ga[1][j][d2]);
                    float gg = tanh_f(ga[2][j][d2]);
                    float og = sigf(ga[3][j][d2]);
                    float c2v = fmaf(fg, ca[d2], ig * gg);
                    float h2v = og * tanh_f(c2v);
                    if (st < Lloc[d2]) {
                        ca[d2] = c2v;
                        ha[d2] = h2v;
                        sa[d2] += h2v;
                    }
                }
                *(float4*)(cs + h * TILE1 + dbase) = make_float4(ca[0], ca[1], ca[2], ca[3]);
                *(float4*)(xh + (128 + h) * TILE1 + dbase) = make_float4(ha[0], ha[1], ha[2], ha[3]);
                *(float4*)(ss + h * TILE1 + dbase) = make_float4(sa[0], sa[1], sa[2], sa[3]);
            }
        }
        __syncthreads();
    }

    // epilogue: doc_emb[doc][dir*128 + h] = sum / len
    {
        const int dbase = dg << 2;
        #pragma unroll
        for (int j = 0; j < 4; j++) {
            int h = (gq << 2) + j;
            #pragma unroll
            for (int d2 = 0; d2 < 4; d2++) {
                int d = dbase + d2;
                float v = ss[h * TILE1 + d] / (float)Ls[d];
                g_demb[(size_t)Did[d] * 256 + dir * 128 + h] = v;
            }
        }
    }
}

// ---------------------------------------------------------------------------
// Layer 2: BiLSTM over nodes (K<=8 steps, input 256, H2=64) + mask + output.
// One CTA = 8 nodes x 1 direction. Thread: 1 hid x 4 gate-types x 2 nodes.
// ---------------------------------------------------------------------------
__global__ void __launch_bounds__(256, 1)
lstm2_kernel(const int* __restrict__ nidx, const int* __restrict__ nlens,
             const int* __restrict__ gnum, float* __restrict__ out) {
    extern __shared__ float sm[];
    float* xh = sm;                 // [320][8]: k<256 x, k>=256 h
    float* cs = sm + 2560;          // [64][8]
    float* ss = sm + 3072;          // [64][8]
    float* wb = sm + 3584;          // [2][KC2][256]
    int*   Ls = (int*)(sm + 3584 + 2 * KC2 * GATES2);    // [8]

    const int tid  = threadIdx.x;
    const int dir  = blockIdx.y;
    const int tile = blockIdx.x;
    const float* Wt = g_Wt2 + (size_t)dir * KTOT2 * GATES2;

    if (tid < TILE2) Ls[tid] = nlens[tile * TILE2 + tid];
    // zero h-part of xh (2048..2559), c (2560..3071), sum (3072..3583)
    for (int i = tid; i < 1536; i += 256) sm[2048 + i] = 0.f;
    __syncthreads();

    int maxlen = 0;
    #pragma unroll
    for (int i = 0; i < TILE2; i++) maxlen = max(maxlen, Ls[i]);

    const int ng = tid & 3;     // node group: nodes 2*ng, 2*ng+1
    const int hh = tid >> 2;    // hid 0..63
    const int xn = tid >> 5;    // x-gather: node 0..7
    const int xq = tid & 31;    // x-gather: 8-float slice

    for (int st = 0; st < maxlen; ++st) {
        // issue W chunk 0
        {
            const float4* src = (const float4*)Wt + tid;
            float4* dst = (float4*)wb + tid;
            #pragma unroll
            for (int q = 0; q < 16; q++) cp_async16(dst + 256 * q, src + 256 * q);
            cp_commit();
        }
        // gather x from doc embeddings
        {
            int L  = Ls[xn];
            int te = (dir == 0) ? st : (L - 1 - st);
            te = min(max(te, 0), KSTEPS - 1);
            int gn = tile * TILE2 + xn;
            int didx = nidx[gn * KSTEPS + te];
            const float4* row = (const float4*)(g_demb + (size_t)didx * 256);
            #pragma unroll
            for (int r = 0; r < 2; r++) {
                float4 v = row[xq * 2 + r];
                int k0 = xq * 8 + r * 4;
                xh[(k0 + 0) * TILE2 + xn] = v.x;
                xh[(k0 + 1) * TILE2 + xn] = v.y;
                xh[(k0 + 2) * TILE2 + xn] = v.z;
                xh[(k0 + 3) * TILE2 + xn] = v.w;
            }
        }
        __syncthreads();

        // acc[b]: packed pair over the 2 nodes {n0, n1}
        unsigned long long acc[4];
        #pragma unroll
        for (int b = 0; b < 4; b++) acc[b] = 0ull;

        for (int n = 0; n < NCH2; n++) {
            if (n + 1 < NCH2) {
                const float4* src = (const float4*)(Wt + (size_t)(n + 1) * KC2 * GATES2) + tid;
                float4* dst = (float4*)(wb + ((n + 1) & 1) * (KC2 * GATES2)) + tid;
                #pragma unroll
                for (int q = 0; q < 16; q++) cp_async16(dst + 256 * q, src + 256 * q);
                cp_commit();
                cp_wait1();
            } else {
                cp_wait0();
            }
            __syncthreads();

            const float* W  = wb + (n & 1) * (KC2 * GATES2);
            const float* xk = xh + n * KC2 * TILE2;
            #pragma unroll 4
            for (int kc = 0; kc < KC2; kc++) {
                unsigned long long xv = *(const unsigned long long*)(xk + kc * TILE2 + (ng << 1));
                #pragma unroll
                for (int b = 0; b < 4; b++) {
                    unsigned long long wp = dup2(W[kc * GATES2 + b * HID2 + hh]);
                    ffma2(acc[b], wp, xv);
                }
            }
            __syncthreads();
        }

        // state update
        {
            float2 gi2 = unpack2(acc[0]);
            float2 gf2 = unpack2(acc[1]);
            float2 gg2 = unpack2(acc[2]);
            float2 go2 = unpack2(acc[3]);
            float gia[2] = { gi2.x, gi2.y };
            float gfa[2] = { gf2.x, gf2.y };
            float gga[2] = { gg2.x, gg2.y };
            float goa[2] = { go2.x, go2.y };
            #pragma unroll
            for (int e = 0; e < 2; e++) {
                int nd = (ng << 1) + e;
                float co = cs[hh * TILE2 + nd];
                float ho = xh[(256 + hh) * TILE2 + nd];
                float so = ss[hh * TILE2 + nd];
                float ig = sigf(gia[e]);
                float fg = sigf(gfa[e]);
                float gg = tanh_f(gga[e]);
                float og = sigf(goa[e]);
                float c2v = fmaf(fg, co, ig * gg);
                float h2v = og * tanh_f(c2v);
                bool act = st < Ls[nd];
                cs[hh * TILE2 + nd] = act ? c2v : co;
                xh[(256 + hh) * TILE2 + nd] = act ? h2v : ho;
                ss[hh * TILE2 + nd] = act ? (so + h2v) : so;
            }
        }
        __syncthreads();
    }

    // epilogue: masked output + gmask
    {
        #pragma unroll
        for (int e = 0; e < 2; e++) {
            int nd = (ng << 1) + e;
            int gn = tile * TILE2 + nd;
            int gi = gn >> 6;
            int ni = gn & 63;
            float gm = (ni < gnum[gi]) ? 1.f : 0.f;
            float v = ss[hh * TILE2 + nd] / (float)Ls[nd] * gm;
            out[(size_t)gn * 128 + dir * 64 + hh] = v;
            if (dir == 0 && hh == 0) out[NNODES * 128 + gn] = gm;
        }
    }
}

// ---------------------------------------------------------------------------
// Launch
// ---------------------------------------------------------------------------
extern "C" void kernel_launch(void* const* d_in, const int* in_sizes, int n_in,
                              void* d_out, int out_size) {
    const float* docs  = (const float*)d_in[0];
    const int*   dlens = (const int*)  d_in[1];
    const int*   nidx  = (const int*)  d_in[2];
    const int*   nlens = (const int*)  d_in[3];
    const int*   gnum  = (const int*)  d_in[4];
    const float* Wih1f = (const float*)d_in[5];
    const float* Whh1f = (const float*)d_in[6];
    const float* Wih1b = (const float*)d_in[7];
    const float* Whh1b = (const float*)d_in[8];
    const float* Wih2f = (const float*)d_in[9];
    const float* Whh2f = (const float*)d_in[10];
    const float* Wih2b = (const float*)d_in[11];
    const float* Whh2b = (const float*)d_in[12];
    float* out = (float*)d_out;

    const size_t sm1 = (size_t)(16384 + 2 * KC1 * GATES) * 4 + (TILE1 * 2) * 4;    // 196864 B
    const size_t sm2 = (size_t)(3584 + 2 * KC2 * GATES2) * 4 + TILE2 * 4 + 32;     // ~145472 B
    cudaFuncSetAttribute(lstm1_kernel, cudaFuncAttributeMaxDynamicSharedMemorySize, (int)sm1);
    cudaFuncSetAttribute(lstm2_kernel, cudaFuncAttributeMaxDynamicSharedMemorySize, (int)sm2);

    transpose1_kernel<<<dim3(512, 2), 256>>>(Wih1f, Whh1f, Wih1b, Whh1b);
    transpose2_kernel<<<dim3(256, 2), 320>>>(Wih2f, Whh2f, Wih2b, Whh2b);
    sort_kernel<<<1, 1024>>>(dlens);
    lstm1_kernel<<<dim3(TDOCS / TILE1, 2), 256, sm1>>>(docs, dlens);
    lstm2_kernel<<<dim3(NNODES / TILE2, 2), 256, sm2>>>(nidx, nlens, gnum, out);
    (void)in_sizes; (void)n_in; (void)out_size;
}